// round 16
// baseline (speedup 1.0000x reference)
#include <cuda_runtime.h>
#include <math.h>

#define BB 8
#define FR 257
#define FRP 288                 /* padded row (9*32) for g_hp: unguarded k-tiles */
#define FWR 320                 /* padded g-rows for g_fWp */
#define FWC 288                 /* padded f-cols for g_fWp */
#define TT 300
#define CC 64
#define CPP 16
#define NN (BB*TT)              /* 2400 */
#define NNP 2432                /* padded n for g_hp (19*128) */
#define NFP ((size_t)NNP*FRP)
#define LN_EPS 1e-5f
#define CH 65
#define XSS 68                  /* xs/ys row stride (floats) */

// Scratch (device globals: allocation-free; zero-initialized at module load —
// padding regions are never written and stay exactly 0)
__device__ float g_x1[(size_t)NN*FR*CC];       // stage-1 output  [n][f][c]
__device__ float g_hp[(size_t)CPP*NNP*FRP];    // reduced hidden  [p][npad][fpad]
__device__ float g_hq[(size_t)NN*FR*CPP];      // fW GEMM output  [n][f][p]
__device__ float g_fWp[(size_t)CPP*FWR*FWC];   // padded fW       [p][gpad][fpad]

__device__ __forceinline__ float to_tf32(float x) {
  float y;
  asm("cvt.rna.tf32.f32 %0, %1;" : "=f"(y) : "f"(x));
  return y;
}
#define MMA_TF32(ac, a0,a1,a2,a3, b0,b1) \
  asm volatile("mma.sync.aligned.m16n8k8.row.col.f32.tf32.tf32.f32 " \
    "{%0,%1,%2,%3},{%4,%5,%6,%7},{%8,%9},{%0,%1,%2,%3};" \
    : "+f"((ac)[0]), "+f"((ac)[1]), "+f"((ac)[2]), "+f"((ac)[3]) \
    : "r"(a0), "r"(a1), "r"(a2), "r"(a3), "r"(b0), "r"(b1))

#define WRED2(S,Q) { _Pragma("unroll") for (int _o=16;_o;_o>>=1){ \
  (S) += __shfl_xor_sync(0xffffffffu,(S),_o); \
  (Q) += __shfl_xor_sync(0xffffffffu,(Q),_o);} }

// MMA grouped conv: warp `w` = channel-group w. ysc = LN-output buffer with
// valid rows [0,ne), zero rows at -1 and ne. Rows beyond ne may hold garbage:
// each A-row feeds only its own (predicated-off) output row. Output for
// local f in [0,nf): acc[q] + conv-bias -> leaky -> CODE(fl, c, lv).
#define CONV_MMA(CBOFS, CODE) { \
  unsigned bb[3][2]; \
  _Pragma("unroll") \
  for (int kk = 0; kk < 3; ++kk) { \
    bb[kk][0] = __float_as_uint(wcg[((wid*3+kk)*8 + grp)*9 + tig]); \
    bb[kk][1] = __float_as_uint(wcg[((wid*3+kk)*8 + grp)*9 + tig + 4]); \
  } \
  const float cb0 = par[(CBOFS) + wid*8 + 2*tig]; \
  const float cb1 = par[(CBOFS) + wid*8 + 2*tig + 1]; \
  const int ntiles = (nf + 15) >> 4; \
  for (int mt = 0; mt < ntiles; ++mt) { \
    float acc[4] = {0.f, 0.f, 0.f, 0.f}; \
    const int fb = mt*16 + off - 1; \
    _Pragma("unroll") \
    for (int kk = 0; kk < 3; ++kk) { \
      const int r = fb + kk; \
      unsigned a0 = __float_as_uint(ysc[(r+grp)*XSS   + wid*8 + tig]); \
      unsigned a1 = __float_as_uint(ysc[(r+grp+8)*XSS + wid*8 + tig]); \
      unsigned a2 = __float_as_uint(ysc[(r+grp)*XSS   + wid*8 + tig + 4]); \
      unsigned a3 = __float_as_uint(ysc[(r+grp+8)*XSS + wid*8 + tig + 4]); \
      MMA_TF32(acc, a0,a1,a2,a3, bb[kk][0], bb[kk][1]); \
    } \
    _Pragma("unroll") \
    for (int q = 0; q < 4; ++q) { \
      const int fl = mt*16 + grp + ((q >> 1) << 3); \
      if (fl < nf) { \
        const int c = wid*8 + 2*tig + (q & 1); \
        float a = acc[q] + ((q & 1) ? cb1 : cb0); \
        float lv = (a >= 0.f) ? a : alpha*a; \
        CODE \
      } \
    } \
  } }

// ---------------------------------------------------------------------------
// k_prep: pad fW [p][g<257][f<257] -> g_fWp [p][320][288]
// ---------------------------------------------------------------------------
__global__ __launch_bounds__(256) void k_prep(const float* __restrict__ fW)
{
  size_t total = (size_t)CPP*FR*FR;
  for (size_t i = (size_t)blockIdx.x*256 + threadIdx.x; i < total;
       i += (size_t)gridDim.x*256) {
    int p = (int)(i / (FR*FR));
    int r = (int)((i / FR) % FR);
    int f = (int)(i % FR);
    g_fWp[((size_t)p*FWR + r)*FWC + f] = fW[i];
  }
}

// ---------------------------------------------------------------------------
// K1: LN1 + MMA grouped conv #1 + LN2 + (MMA reduce || x1 store)
// ---------------------------------------------------------------------------
__global__ __launch_bounds__(256, 4) void k_freq1(
    const float* __restrict__ h,
    const float* __restrict__ g1, const float* __restrict__ b1,
    const float* __restrict__ w1, const float* __restrict__ cb1,
    const float* __restrict__ a1,
    const float* __restrict__ fg, const float* __restrict__ fbv,
    const float* __restrict__ rw_, const float* __restrict__ rb_)
{
  extern __shared__ float sm[];
  float* xs  = sm;              // [67*68]
  float* ysb = xs + 67*XSS;     // [83*68]  rows -1..81 of conv-view
  float* wcg = ysb + 83*XSS;    // [8g][3kk][8c'][9] tf32 conv weights
  float* rwT = wcg + 8*3*8*9;   // [64*17]  tf32 [c][p]
  float* par = rwT + 64*17;     // g1|b1|cb|fg|fb (64 each) + rb(16)
  float* ysc = ysb + XSS;       // conv-view base (row -1 = ysb row 0)

  const int tid = threadIdx.x;
  const int n = blockIdx.x;
  const int b = n / TT, t = n % TT;
  const int f0 = blockIdx.y * CH;
  const int f1 = min(FR, f0 + CH);
  const int nf = f1 - f0;
  const int e0 = (f0 > 0) ? f0 - 1 : 0;
  const int e1 = (f1 < FR) ? f1 + 1 : FR;
  const int ne = e1 - e0;
  const int off = (f0 > 0) ? 1 : 0;

  if (tid < CC) {
    par[tid]     = g1[tid];  par[64+tid]  = b1[tid];  par[128+tid] = cb1[tid];
    par[192+tid] = fg[tid];  par[256+tid] = fbv[tid];
  }
  if (tid >= 64 && tid < 64+CPP) par[320 + (tid-64)] = rb_[tid-64];
  for (int i = tid; i < 8*3*64; i += 256) {
    int g = i / 192, r = i % 192, kk = r >> 6, s = r & 63;
    int cp = s >> 3, ci = s & 7;
    wcg[((g*3+kk)*8 + cp)*9 + ci] = to_tf32(w1[(g*8+cp)*24 + ci*3 + kk]);
  }
  for (int i = tid; i < CC*CPP; i += 256) {
    int c = i >> 4, p = i & 15;
    rwT[c*17 + p] = to_tf32(rw_[p*64 + c]);
  }
  // zero only the true halo rows: ysc[-1] and ysc[ne]
  for (int i = tid; i < XSS; i += 256) {
    ysb[i] = 0.f;
    ysb[(ne+1)*XSS + i] = 0.f;
  }

  const float alpha = __ldg(a1);
  const float* hbase = h + ((size_t)b*FR*TT + t)*CC;
  for (int i = tid; i < ne*16; i += 256) {
    int r = i >> 4, q = i & 15;
    *(float4*)(xs + r*XSS + q*4) =
        ((const float4*)(hbase + (size_t)(e0+r)*TT*CC))[q];
  }
  __syncthreads();

  const int wid = tid >> 5, lane = tid & 31;
  const int grp = lane >> 2, tig = lane & 3;

  // LN1 over all ne rows -> ysc (tf32)
  for (int r = wid; r < ne; r += 8) {
    float v0 = xs[r*XSS+lane], v1 = xs[r*XSS+lane+32];
    float s = v0+v1, q = v0*v0+v1*v1;
    WRED2(s,q)
    float m = s*(1.f/64.f);
    float rr = rsqrtf(fmaxf(q*(1.f/64.f)-m*m, 0.f)+LN_EPS);
    ysc[r*XSS+lane]    = to_tf32((v0-m)*rr*par[lane]    + par[64+lane]);
    ysc[r*XSS+lane+32] = to_tf32((v1-m)*rr*par[32+lane] + par[96+lane]);
  }
  __syncthreads();

  // MMA grouped conv + leaky + residual (update xs in place)
  CONV_MMA(128, {
    int xr = fl + off;
    xs[xr*XSS + c] += lv;
  })
  __syncthreads();

  // LN2 -> ysc rows 0..nf-1 (tf32); x1 store deferred to reduce phase
  for (int fo = wid; fo < nf; fo += 8) {
    int le = fo + off;
    float v0 = xs[le*XSS+lane], v1 = xs[le*XSS+lane+32];
    float s = v0+v1, q = v0*v0+v1*v1;
    WRED2(s,q)
    float m = s*(1.f/64.f);
    float rr = rsqrtf(fmaxf(q*(1.f/64.f)-m*m, 0.f)+LN_EPS);
    ysc[fo*XSS+lane]    = to_tf32((v0-m)*rr*par[192+lane] + par[256+lane]);
    ysc[fo*XSS+lane+32] = to_tf32((v1-m)*rr*par[224+lane] + par[288+lane]);
  }
  __syncthreads();

  if (wid < 5) {
    // MMA reduce: warp w (0..4) handles f-tile w*16, both p-tiles of 8
    const int fr0 = wid*16;
    float acc[2][4] = {{0.f,0.f,0.f,0.f},{0.f,0.f,0.f,0.f}};
    #pragma unroll
    for (int kc = 0; kc < 8; ++kc) {
      const int cc = kc*8;
      unsigned a0 = __float_as_uint(ysc[(fr0+grp)*XSS + cc + tig]);
      unsigned a1 = __float_as_uint(ysc[(fr0+grp+8)*XSS + cc + tig]);
      unsigned a2 = __float_as_uint(ysc[(fr0+grp)*XSS + cc + tig + 4]);
      unsigned a3 = __float_as_uint(ysc[(fr0+grp+8)*XSS + cc + tig + 4]);
      #pragma unroll
      for (int nt = 0; nt < 2; ++nt) {
        unsigned b0 = __float_as_uint(rwT[(cc+tig)*17 + nt*8 + grp]);
        unsigned b1 = __float_as_uint(rwT[(cc+tig+4)*17 + nt*8 + grp]);
        MMA_TF32(acc[nt], a0,a1,a2,a3, b0,b1);
      }
    }
    #pragma unroll
    for (int nt = 0; nt < 2; ++nt)
      #pragma unroll
      for (int q = 0; q < 4; ++q) {
        int frow = fr0 + grp + ((q >> 1) << 3);
        int p = nt*8 + 2*tig + (q & 1);
        if (frow < nf) {
          float v = acc[nt][q] + par[320+p];
          g_hp[(size_t)p*NFP + (size_t)n*FRP + f0 + frow] = v/(1.f+__expf(-v));
        }
      }
  } else {
    // warps 5..7: coalesced x1 store (xs rows are final; runs with reduce)
    float* x1dst = g_x1 + ((size_t)n*FR + f0)*CC;
    const int base = (wid-5)*32 + lane;
    for (int i = base; i < nf*16; i += 96) {
      int r = i >> 4, q = i & 15;
      *(float4*)(x1dst + (size_t)r*64 + q*4) =
          *(const float4*)(xs + (r+off)*XSS + q*4);
    }
  }
}

// ---------------------------------------------------------------------------
// K2: per-channel GEMM  hq[n,g,p] = sum_f hp[p,n,f] * fW[p,g,f] + fB[p,g]
//     tf32 mma m16n8k8, 128x64 tile, reg-prefetch 2-buf, unguarded staging
// ---------------------------------------------------------------------------
#define K2_LOAD(FT) { \
  _Pragma("unroll") for (int j = 0; j < 4; ++j) { \
    int u = tid + j*256; int row = u >> 3, kq = u & 7; \
    ra[j] = *(const float4*)&A[(size_t)row*FRP + (FT) + kq*4]; \
  } \
  _Pragma("unroll") for (int j = 0; j < 2; ++j) { \
    int u = tid + j*256; int row = u >> 3, kq = u & 7; \
    rb4[j] = *(const float4*)&Bw[(size_t)row*FWC + (FT) + kq*4]; \
  } }

#define K2_STORE(BUF) { \
  _Pragma("unroll") for (int j = 0; j < 4; ++j) { \
    int u = tid + j*256; int row = u >> 3, kq = u & 7; \
    *(float4*)&As[BUF][row*36 + kq*4] = ra[j]; \
  } \
  _Pragma("unroll") for (int j = 0; j < 2; ++j) { \
    int u = tid + j*256; int row = u >> 3, kq = u & 7; \
    *(float4*)&Bs[BUF][row*36 + kq*4] = rb4[j]; \
  } }

__global__ __launch_bounds__(256) void k_fgemm(const float* __restrict__ fB)
{
  __shared__ float As[2][128*36];
  __shared__ float Bs[2][64*36];
  __shared__ float fBs[64];
  const int p  = blockIdx.z;
  const int n0 = blockIdx.x * 128, g0 = blockIdx.y * 64;
  const float* A  = g_hp  + (size_t)p*NFP + (size_t)n0*FRP; // rows>=NN are 0
  const float* Bw = g_fWp + ((size_t)p*FWR + g0)*FWC;       // rows>=FR are 0
  const int tid = threadIdx.x;
  const int lane = tid & 31, wid = tid >> 5;
  const int wm = (wid & 3) * 32, wn = (wid >> 2) * 32;
  const int grp = lane >> 2, tig = lane & 3;
  if (tid < 64) fBs[tid] = (g0+tid < FR) ? fB[p*FR + g0 + tid] : 0.f;

  float acc[2][4][4];
  #pragma unroll
  for (int i = 0; i < 2; ++i)
    #pragma unroll
    for (int j = 0; j < 4; ++j)
      #pragma unroll
      for (int q = 0; q < 4; ++q) acc[i][j][q] = 0.f;

  float4 ra[4]; float4 rb4[2];
  K2_LOAD(0)
  K2_STORE(0)
  __syncthreads();

  for (int it = 0; it < 9; ++it) {
    if (it < 8) { K2_LOAD((it+1)*32) }
    const int cur = it & 1;
    #pragma unroll
    for (int k8 = 0; k8 < 4; ++k8) {
      const int col = k8*8 + tig;
      unsigned a[2][4];
      #pragma unroll
      for (int mt = 0; mt < 2; ++mt) {
        int r = wm + mt*16 + grp;
        a[mt][0] = __float_as_uint(As[cur][r*36 + col]);
        a[mt][1] = __float_as_uint(As[cur][(r+8)*36 + col]);
        a[mt][2] = __float_as_uint(As[cur][r*36 + col + 4]);
        a[mt][3] = __float_as_uint(As[cur][(r+8)*36 + col + 4]);
      }
      #pragma unroll
      for (int nt = 0; nt < 4; ++nt) {
        int rbw = wn + nt*8 + grp;
        unsigned b0 = __float_as_uint(Bs[cur][rbw*36 + col]);
        unsigned b1 = __float_as_uint(Bs[cur][rbw*36 + col + 4]);
        #pragma unroll
        for (int mt = 0; mt < 2; ++mt)
          MMA_TF32(acc[mt][nt], a[mt][0],a[mt][1],a[mt][2],a[mt][3], b0,b1);
      }
    }
    if (it < 8) {
      K2_STORE((it+1) & 1)
      __syncthreads();
    }
  }

  #pragma unroll
  for (int mt = 0; mt < 2; ++mt) {
    #pragma unroll
    for (int nt = 0; nt < 4; ++nt) {
      int r = n0 + wm + mt*16 + grp;
      int gl = wn + nt*8 + tig*2;
      int g = g0 + gl;
      #pragma unroll
      for (int q = 0; q < 4; ++q) {
        int rr = r + (q >> 1) * 8;
        int gc = g + (q & 1);
        if (rr < NN && gc < FR)
          g_hq[((size_t)rr*FR + gc)*CPP + p] = acc[mt][nt][q] + fBs[gl + (q&1)];
      }
    }
  }
}

// ---------------------------------------------------------------------------
// K3: MMA expand + silu + residual, LN, MMA grouped conv #2, coalesced out
// ---------------------------------------------------------------------------
__global__ __launch_bounds__(256, 4) void k_freq2(
    float* __restrict__ out,
    const float* __restrict__ ew_, const float* __restrict__ eb_,
    const float* __restrict__ g2, const float* __restrict__ b2,
    const float* __restrict__ w2_, const float* __restrict__ cb2,
    const float* __restrict__ a2)
{
  extern __shared__ float sm[];
  float* xs  = sm;              // [67*68]
  float* ysb = xs + 67*XSS;     // [83*68]; hqs (80*20 tf32) aliases its start
  float* wcg = ysb + 83*XSS;    // [8g][3kk][8c'][9] tf32 conv weights
  float* ewt = wcg + 8*3*8*9;   // [64*17]  tf32 [c][p]
  float* par = ewt + 64*17;     // eb|g2|b2|cb2 (64 each)
  float* ysc = ysb + XSS;
  float* hqs = ysb;             // aliased: dead once LN phase starts

  const int tid = threadIdx.x;
  const int n = blockIdx.x;
  const int b = n / TT, t = n % TT;
  const int f0 = blockIdx.y * CH;
  const int f1 = min(FR, f0 + CH);
  const int nf = f1 - f0;
  const int e0 = (f0 > 0) ? f0 - 1 : 0;
  const int e1 = (f1 < FR) ? f1 + 1 : FR;
  const int ne = e1 - e0;
  const int off = (f0 > 0) ? 1 : 0;

  if (tid < CC) {
    par[tid] = eb_[tid]; par[64+tid] = g2[tid];
    par[128+tid] = b2[tid]; par[192+tid] = cb2[tid];
  }
  for (int i = tid; i < 8*3*64; i += 256) {
    int g = i / 192, r = i % 192, kk = r >> 6, s = r & 63;
    int cp = s >> 3, ci = s & 7;
    wcg[((g*3+kk)*8 + cp)*9 + ci] = to_tf32(w2_[(g*8+cp)*24 + ci*3 + kk]);
  }
  for (int i = tid; i < CC*CPP; i += 256) {
    int c = i >> 4, p = i & 15;
    ewt[c*17 + p] = to_tf32(ew_[c*CPP + p]);
  }
  const float alpha = __ldg(a2);
  const float4* x1src = (const float4*)(g_x1 + ((size_t)n*FR + e0)*CC);
  for (int i = tid; i < ne*16; i += 256) {
    int r = i >> 4, q = i & 15;
    *(float4*)(xs + r*XSS + q*4) = x1src[i];
  }
  const float4* hqsrc = (const float4*)(g_hq + ((size_t)n*FR + e0)*CPP);
  for (int i = tid; i < ne*4; i += 256) {
    int r = i >> 2, q = i & 3;
    float4 v = hqsrc[i];
    v.x = to_tf32(v.x); v.y = to_tf32(v.y); v.z = to_tf32(v.z); v.w = to_tf32(v.w);
    *(float4*)(hqs + r*20 + q*4) = v;
  }
  __syncthreads();

  const int wid = tid >> 5, lane = tid & 31;
  const int grp = lane >> 2, tig = lane & 3;

  // MMA expand: warp w = c-tile w*8, 5 f-tiles of 16; then silu + residual
  {
    float acc[5][4];
    #pragma unroll
    for (int mt = 0; mt < 5; ++mt)
      #pragma unroll
      for (int q = 0; q < 4; ++q) acc[mt][q] = 0.f;
    #pragma unroll
    for (int kc = 0; kc < 2; ++kc) {
      unsigned b0 = __float_as_uint(ewt[(wid*8+grp)*17 + kc*8 + tig]);
      unsigned b1 = __float_as_uint(ewt[(wid*8+grp)*17 + kc*8 + tig + 4]);
      #pragma unroll
      for (int mt = 0; mt < 5; ++mt) {
        unsigned a0 = __float_as_uint(hqs[(mt*16+grp)*20 + kc*8 + tig]);
        unsigned a1 = __float_as_uint(hqs[(mt*16+grp+8)*20 + kc*8 + tig]);
        unsigned a2 = __float_as_uint(hqs[(mt*16+grp)*20 + kc*8 + tig + 4]);
        unsigned a3 = __float_as_uint(hqs[(mt*16+grp+8)*20 + kc*8 + tig + 4]);
        MMA_TF32(acc[mt], a0,a1,a2,a3, b0,b1);
      }
    }
    __syncthreads();   // all hqs reads complete before xs update / ysb reuse
    #pragma unroll
    for (int mt = 0; mt < 5; ++mt)
      #pragma unroll
      for (int q = 0; q < 4; ++q) {
        int f = mt*16 + grp + ((q >> 1) << 3);
        int c = wid*8 + 2*tig + (q & 1);
        if (f < ne) {
          float v = acc[mt][q] + par[c];
          xs[f*XSS+c] += v/(1.f+__expf(-v));
        }
      }
  }
  __syncthreads();

  // zero only true halo rows (ysb now free), LN over all ne rows -> ysc (tf32)
  for (int i = tid; i < XSS; i += 256) {
    ysb[i] = 0.f;
    ysb[(ne+1)*XSS + i] = 0.f;
  }
  for (int r = wid; r < ne; r += 8) {
    float v0 = xs[r*XSS+lane], v1 = xs[r*XSS+lane+32];
    float s = v0+v1, q = v0*v0+v1*v1;
    WRED2(s,q)
    float m = s*(1.f/64.f);
    float rr = rsqrtf(fmaxf(q*(1.f/64.f)-m*m, 0.f)+LN_EPS);
    ysc[r*XSS+lane]    = to_tf32((v0-m)*rr*par[64+lane] + par[128+lane]);
    ysc[r*XSS+lane+32] = to_tf32((v1-m)*rr*par[96+lane] + par[160+lane]);
  }
  __syncthreads();

  // MMA grouped conv #2 + leaky + residual -> xs
  CONV_MMA(192, {
    int xr = fl + off;
    xs[xr*XSS + c] += lv;
  })
  __syncthreads();

  // coalesced copy xs rows [off, off+nf) -> out rows [f0, f1)
  float* obase = out + ((size_t)b*FR*TT + t)*CC;
  for (int i = tid; i < nf*16; i += 256) {
    int r = i >> 4, q = i & 15;
    *(float4*)(obase + (size_t)(f0+r)*TT*CC + q*4) =
        *(const float4*)(xs + (r+off)*XSS + q*4);
  }
}

// ---------------------------------------------------------------------------
extern "C" void kernel_launch(void* const* d_in, const int* in_sizes, int n_in,
                              void* d_out, int out_size)
{
  const float* h     = (const float*)d_in[0];
  const float* fc1g  = (const float*)d_in[1];
  const float* fc1b  = (const float*)d_in[2];
  const float* fc1w  = (const float*)d_in[3];
  const float* fc1cb = (const float*)d_in[4];
  const float* fc1a  = (const float*)d_in[5];
  const float* fblg  = (const float*)d_in[6];
  const float* fblb  = (const float*)d_in[7];
  const float* redw  = (const float*)d_in[8];
  const float* redb  = (const float*)d_in[9];
  const float* fW    = (const float*)d_in[10];
  const float* fB    = (const float*)d_in[11];
  const float* expw  = (const float*)d_in[12];
  const float* expb  = (const float*)d_in[13];
  const float* fc2g  = (const float*)d_in[14];
  const float* fc2b  = (const float*)d_in[15];
  const float* fc2w  = (const float*)d_in[16];
  const float* fc2cb = (const float*)d_in[17];
  const float* fc2a  = (const float*)d_in[18];
  float* out = (float*)d_out;

  const int SM1 = (67*XSS + 83*XSS + 8*3*8*9 + 64*17 + 336) * 4;
  const int SM3 = (67*XSS + 83*XSS + 8*3*8*9 + 64*17 + 256) * 4;
  cudaFuncSetAttribute(k_freq1, cudaFuncAttributeMaxDynamicSharedMemorySize, SM1);
  cudaFuncSetAttribute(k_freq2, cudaFuncAttributeMaxDynamicSharedMemorySize, SM3);

  k_prep<<<528, 256>>>(fW);
  dim3 g1(NN, 4);
  k_freq1<<<g1, 256, SM1>>>(h, fc1g, fc1b, fc1w, fc1cb, fc1a,
                            fblg, fblb, redw, redb);
  dim3 gg((NN+127)/128, (FR+63)/64, CPP);
  k_fgemm<<<gg, 256>>>(fB);
  dim3 g3(NN, 4);
  k_freq2<<<g3, 256, SM3>>>(out, expw, expb, fc2g, fc2b, fc2w, fc2cb, fc2a);
}

// round 17
// speedup vs baseline: 1.0099x; 1.0099x over previous
#include <cuda_runtime.h>
#include <math.h>

#define BB 8
#define FR 257
#define FRP 288                 /* padded row (9*32) for g_hp: unguarded k-tiles */
#define FWR 320                 /* padded g-rows for g_fWp */
#define FWC 288                 /* padded f-cols for g_fWp */
#define TT 300
#define CC 64
#define CPP 16
#define NN (BB*TT)              /* 2400 */
#define NNP 2432                /* padded n for g_hp (19*128) */
#define NFP ((size_t)NNP*FRP)
#define LN_EPS 1e-5f
#define CH 52                   /* F-chunk; 5 chunks: 52*4 + 49 */
#define NCH 5
#define XROWS 54                /* xs rows: ne <= CH+2 */
#define YROWS 56                /* ysb rows: ne+2 */
#define XSS 68                  /* xs/ys row stride (floats) */

// Scratch (device globals: allocation-free; zero-initialized at module load —
// padding regions are never written and stay exactly 0)
__device__ float g_x1[(size_t)NN*FR*CC];       // stage-1 output  [n][f][c]
__device__ float g_hp[(size_t)CPP*NNP*FRP];    // reduced hidden  [p][npad][fpad]
__device__ float g_hq[(size_t)NN*FR*CPP];      // fW GEMM output  [n][f][p]
__device__ float g_fWp[(size_t)CPP*FWR*FWC];   // padded fW       [p][gpad][fpad]

__device__ __forceinline__ float to_tf32(float x) {
  float y;
  asm("cvt.rna.tf32.f32 %0, %1;" : "=f"(y) : "f"(x));
  return y;
}
#define MMA_TF32(ac, a0,a1,a2,a3, b0,b1) \
  asm volatile("mma.sync.aligned.m16n8k8.row.col.f32.tf32.tf32.f32 " \
    "{%0,%1,%2,%3},{%4,%5,%6,%7},{%8,%9},{%0,%1,%2,%3};" \
    : "+f"((ac)[0]), "+f"((ac)[1]), "+f"((ac)[2]), "+f"((ac)[3]) \
    : "r"(a0), "r"(a1), "r"(a2), "r"(a3), "r"(b0), "r"(b1))

#define WRED2(S,Q) { _Pragma("unroll") for (int _o=16;_o;_o>>=1){ \
  (S) += __shfl_xor_sync(0xffffffffu,(S),_o); \
  (Q) += __shfl_xor_sync(0xffffffffu,(Q),_o);} }

// MMA grouped conv: warp `w` = channel-group w. ysc = LN-output buffer with
// valid rows [0,ne), zero rows at -1 and ne. Rows beyond ne may hold garbage:
// each A-row feeds only its own (predicated-off) output row. Output for
// local f in [0,nf): acc[q] + conv-bias -> leaky -> CODE(fl, c, lv).
#define CONV_MMA(CBOFS, CODE) { \
  unsigned bb[3][2]; \
  _Pragma("unroll") \
  for (int kk = 0; kk < 3; ++kk) { \
    bb[kk][0] = __float_as_uint(wcg[((wid*3+kk)*8 + grp)*9 + tig]); \
    bb[kk][1] = __float_as_uint(wcg[((wid*3+kk)*8 + grp)*9 + tig + 4]); \
  } \
  const float cb0 = par[(CBOFS) + wid*8 + 2*tig]; \
  const float cb1 = par[(CBOFS) + wid*8 + 2*tig + 1]; \
  const int ntiles = (nf + 15) >> 4; \
  for (int mt = 0; mt < ntiles; ++mt) { \
    float acc[4] = {0.f, 0.f, 0.f, 0.f}; \
    const int fb = mt*16 + off - 1; \
    _Pragma("unroll") \
    for (int kk = 0; kk < 3; ++kk) { \
      const int r = fb + kk; \
      unsigned a0 = __float_as_uint(ysc[(r+grp)*XSS   + wid*8 + tig]); \
      unsigned a1 = __float_as_uint(ysc[(r+grp+8)*XSS + wid*8 + tig]); \
      unsigned a2 = __float_as_uint(ysc[(r+grp)*XSS   + wid*8 + tig + 4]); \
      unsigned a3 = __float_as_uint(ysc[(r+grp+8)*XSS + wid*8 + tig + 4]); \
      MMA_TF32(acc, a0,a1,a2,a3, bb[kk][0], bb[kk][1]); \
    } \
    _Pragma("unroll") \
    for (int q = 0; q < 4; ++q) { \
      const int fl = mt*16 + grp + ((q >> 1) << 3); \
      if (fl < nf) { \
        const int c = wid*8 + 2*tig + (q & 1); \
        float a = acc[q] + ((q & 1) ? cb1 : cb0); \
        float lv = (a >= 0.f) ? a : alpha*a; \
        CODE \
      } \
    } \
  } }

// ---------------------------------------------------------------------------
// k_prep: pad fW [p][g<257][f<257] -> g_fWp [p][320][288]
// ---------------------------------------------------------------------------
__global__ __launch_bounds__(256) void k_prep(const float* __restrict__ fW)
{
  size_t total = (size_t)CPP*FR*FR;
  for (size_t i = (size_t)blockIdx.x*256 + threadIdx.x; i < total;
       i += (size_t)gridDim.x*256) {
    int p = (int)(i / (FR*FR));
    int r = (int)((i / FR) % FR);
    int f = (int)(i % FR);
    g_fWp[((size_t)p*FWR + r)*FWC + f] = fW[i];
  }
}

// ---------------------------------------------------------------------------
// K1: LN1 + MMA grouped conv #1 + LN2 + (MMA reduce || x1 store)
// ---------------------------------------------------------------------------
__global__ __launch_bounds__(256, 5) void k_freq1(
    const float* __restrict__ h,
    const float* __restrict__ g1, const float* __restrict__ b1,
    const float* __restrict__ w1, const float* __restrict__ cb1,
    const float* __restrict__ a1,
    const float* __restrict__ fg, const float* __restrict__ fbv,
    const float* __restrict__ rw_, const float* __restrict__ rb_)
{
  extern __shared__ float sm[];
  float* xs  = sm;                 // [XROWS*68]
  float* ysb = xs + XROWS*XSS;     // [YROWS*68]  rows -1..ne of conv-view
  float* wcg = ysb + YROWS*XSS;    // [8g][3kk][8c'][9] tf32 conv weights
  float* rwT = wcg + 8*3*8*9;      // [64*17]  tf32 [c][p]
  float* par = rwT + 64*17;        // g1|b1|cb|fg|fb (64 each) + rb(16)
  float* ysc = ysb + XSS;          // conv-view base (row -1 = ysb row 0)

  const int tid = threadIdx.x;
  const int n = blockIdx.x;
  const int b = n / TT, t = n % TT;
  const int f0 = blockIdx.y * CH;
  const int f1 = min(FR, f0 + CH);
  const int nf = f1 - f0;
  const int e0 = (f0 > 0) ? f0 - 1 : 0;
  const int e1 = (f1 < FR) ? f1 + 1 : FR;
  const int ne = e1 - e0;
  const int off = (f0 > 0) ? 1 : 0;

  if (tid < CC) {
    par[tid]     = g1[tid];  par[64+tid]  = b1[tid];  par[128+tid] = cb1[tid];
    par[192+tid] = fg[tid];  par[256+tid] = fbv[tid];
  }
  if (tid >= 64 && tid < 64+CPP) par[320 + (tid-64)] = rb_[tid-64];
  for (int i = tid; i < 8*3*64; i += 256) {
    int g = i / 192, r = i % 192, kk = r >> 6, s = r & 63;
    int cp = s >> 3, ci = s & 7;
    wcg[((g*3+kk)*8 + cp)*9 + ci] = to_tf32(w1[(g*8+cp)*24 + ci*3 + kk]);
  }
  for (int i = tid; i < CC*CPP; i += 256) {
    int c = i >> 4, p = i & 15;
    rwT[c*17 + p] = to_tf32(rw_[p*64 + c]);
  }
  // zero only the true halo rows: ysc[-1] and ysc[ne]
  for (int i = tid; i < XSS; i += 256) {
    ysb[i] = 0.f;
    ysb[(ne+1)*XSS + i] = 0.f;
  }

  const float alpha = __ldg(a1);
  const float* hbase = h + ((size_t)b*FR*TT + t)*CC;
  for (int i = tid; i < ne*16; i += 256) {
    int r = i >> 4, q = i & 15;
    *(float4*)(xs + r*XSS + q*4) =
        ((const float4*)(hbase + (size_t)(e0+r)*TT*CC))[q];
  }
  __syncthreads();

  const int wid = tid >> 5, lane = tid & 31;
  const int grp = lane >> 2, tig = lane & 3;

  // LN1 over all ne rows -> ysc (tf32)
  for (int r = wid; r < ne; r += 8) {
    float v0 = xs[r*XSS+lane], v1 = xs[r*XSS+lane+32];
    float s = v0+v1, q = v0*v0+v1*v1;
    WRED2(s,q)
    float m = s*(1.f/64.f);
    float rr = rsqrtf(fmaxf(q*(1.f/64.f)-m*m, 0.f)+LN_EPS);
    ysc[r*XSS+lane]    = to_tf32((v0-m)*rr*par[lane]    + par[64+lane]);
    ysc[r*XSS+lane+32] = to_tf32((v1-m)*rr*par[32+lane] + par[96+lane]);
  }
  __syncthreads();

  // MMA grouped conv + leaky + residual (update xs in place)
  CONV_MMA(128, {
    int xr = fl + off;
    xs[xr*XSS + c] += lv;
  })
  __syncthreads();

  // LN2 -> ysc rows 0..nf-1 (tf32); x1 store deferred to reduce phase
  for (int fo = wid; fo < nf; fo += 8) {
    int le = fo + off;
    float v0 = xs[le*XSS+lane], v1 = xs[le*XSS+lane+32];
    float s = v0+v1, q = v0*v0+v1*v1;
    WRED2(s,q)
    float m = s*(1.f/64.f);
    float rr = rsqrtf(fmaxf(q*(1.f/64.f)-m*m, 0.f)+LN_EPS);
    ysc[fo*XSS+lane]    = to_tf32((v0-m)*rr*par[192+lane] + par[256+lane]);
    ysc[fo*XSS+lane+32] = to_tf32((v1-m)*rr*par[224+lane] + par[288+lane]);
  }
  __syncthreads();

  if (wid < 4) {
    // MMA reduce: warp w (0..3) handles f-tile w*16 (4*16=64 >= nf), 2 p-tiles
    const int fr0 = wid*16;
    float acc[2][4] = {{0.f,0.f,0.f,0.f},{0.f,0.f,0.f,0.f}};
    #pragma unroll
    for (int kc = 0; kc < 8; ++kc) {
      const int cc = kc*8;
      unsigned a0 = __float_as_uint(ysc[(fr0+grp)*XSS + cc + tig]);
      unsigned a1 = __float_as_uint(ysc[(fr0+grp+8)*XSS + cc + tig]);
      unsigned a2 = __float_as_uint(ysc[(fr0+grp)*XSS + cc + tig + 4]);
      unsigned a3 = __float_as_uint(ysc[(fr0+grp+8)*XSS + cc + tig + 4]);
      #pragma unroll
      for (int nt = 0; nt < 2; ++nt) {
        unsigned b0 = __float_as_uint(rwT[(cc+tig)*17 + nt*8 + grp]);
        unsigned b1 = __float_as_uint(rwT[(cc+tig+4)*17 + nt*8 + grp]);
        MMA_TF32(acc[nt], a0,a1,a2,a3, b0,b1);
      }
    }
    #pragma unroll
    for (int nt = 0; nt < 2; ++nt)
      #pragma unroll
      for (int q = 0; q < 4; ++q) {
        int frow = fr0 + grp + ((q >> 1) << 3);
        int p = nt*8 + 2*tig + (q & 1);
        if (frow < nf) {
          float v = acc[nt][q] + par[320+p];
          g_hp[(size_t)p*NFP + (size_t)n*FRP + f0 + frow] = v/(1.f+__expf(-v));
        }
      }
  } else {
    // warps 4..7: coalesced x1 store (xs rows are final; runs with reduce)
    float* x1dst = g_x1 + ((size_t)n*FR + f0)*CC;
    const int base = (wid-4)*32 + lane;
    for (int i = base; i < nf*16; i += 128) {
      int r = i >> 4, q = i & 15;
      *(float4*)(x1dst + (size_t)r*64 + q*4) =
          *(const float4*)(xs + (r+off)*XSS + q*4);
    }
  }
}

// ---------------------------------------------------------------------------
// K2: per-channel GEMM  hq[n,g,p] = sum_f hp[p,n,f] * fW[p,g,f] + fB[p,g]
//     tf32 mma m16n8k8, 128x64 tile, reg-prefetch 2-buf, unguarded staging
// ---------------------------------------------------------------------------
#define K2_LOAD(FT) { \
  _Pragma("unroll") for (int j = 0; j < 4; ++j) { \
    int u = tid + j*256; int row = u >> 3, kq = u & 7; \
    ra[j] = *(const float4*)&A[(size_t)row*FRP + (FT) + kq*4]; \
  } \
  _Pragma("unroll") for (int j = 0; j < 2; ++j) { \
    int u = tid + j*256; int row = u >> 3, kq = u & 7; \
    rb4[j] = *(const float4*)&Bw[(size_t)row*FWC + (FT) + kq*4]; \
  } }

#define K2_STORE(BUF) { \
  _Pragma("unroll") for (int j = 0; j < 4; ++j) { \
    int u = tid + j*256; int row = u >> 3, kq = u & 7; \
    *(float4*)&As[BUF][row*36 + kq*4] = ra[j]; \
  } \
  _Pragma("unroll") for (int j = 0; j < 2; ++j) { \
    int u = tid + j*256; int row = u >> 3, kq = u & 7; \
    *(float4*)&Bs[BUF][row*36 + kq*4] = rb4[j]; \
  } }

__global__ __launch_bounds__(256) void k_fgemm(const float* __restrict__ fB)
{
  __shared__ float As[2][128*36];
  __shared__ float Bs[2][64*36];
  __shared__ float fBs[64];
  const int p  = blockIdx.z;
  const int n0 = blockIdx.x * 128, g0 = blockIdx.y * 64;
  const float* A  = g_hp  + (size_t)p*NFP + (size_t)n0*FRP; // rows>=NN are 0
  const float* Bw = g_fWp + ((size_t)p*FWR + g0)*FWC;       // rows>=FR are 0
  const int tid = threadIdx.x;
  const int lane = tid & 31, wid = tid >> 5;
  const int wm = (wid & 3) * 32, wn = (wid >> 2) * 32;
  const int grp = lane >> 2, tig = lane & 3;
  if (tid < 64) fBs[tid] = (g0+tid < FR) ? fB[p*FR + g0 + tid] : 0.f;

  float acc[2][4][4];
  #pragma unroll
  for (int i = 0; i < 2; ++i)
    #pragma unroll
    for (int j = 0; j < 4; ++j)
      #pragma unroll
      for (int q = 0; q < 4; ++q) acc[i][j][q] = 0.f;

  float4 ra[4]; float4 rb4[2];
  K2_LOAD(0)
  K2_STORE(0)
  __syncthreads();

  for (int it = 0; it < 9; ++it) {
    if (it < 8) { K2_LOAD((it+1)*32) }
    const int cur = it & 1;
    #pragma unroll
    for (int k8 = 0; k8 < 4; ++k8) {
      const int col = k8*8 + tig;
      unsigned a[2][4];
      #pragma unroll
      for (int mt = 0; mt < 2; ++mt) {
        int r = wm + mt*16 + grp;
        a[mt][0] = __float_as_uint(As[cur][r*36 + col]);
        a[mt][1] = __float_as_uint(As[cur][(r+8)*36 + col]);
        a[mt][2] = __float_as_uint(As[cur][r*36 + col + 4]);
        a[mt][3] = __float_as_uint(As[cur][(r+8)*36 + col + 4]);
      }
      #pragma unroll
      for (int nt = 0; nt < 4; ++nt) {
        int rbw = wn + nt*8 + grp;
        unsigned b0 = __float_as_uint(Bs[cur][rbw*36 + col]);
        unsigned b1 = __float_as_uint(Bs[cur][rbw*36 + col + 4]);
        #pragma unroll
        for (int mt = 0; mt < 2; ++mt)
          MMA_TF32(acc[mt][nt], a[mt][0],a[mt][1],a[mt][2],a[mt][3], b0,b1);
      }
    }
    if (it < 8) {
      K2_STORE((it+1) & 1)
      __syncthreads();
    }
  }

  #pragma unroll
  for (int mt = 0; mt < 2; ++mt) {
    #pragma unroll
    for (int nt = 0; nt < 4; ++nt) {
      int r = n0 + wm + mt*16 + grp;
      int gl = wn + nt*8 + tig*2;
      int g = g0 + gl;
      #pragma unroll
      for (int q = 0; q < 4; ++q) {
        int rr = r + (q >> 1) * 8;
        int gc = g + (q & 1);
        if (rr < NN && gc < FR)
          g_hq[((size_t)rr*FR + gc)*CPP + p] = acc[mt][nt][q] + fBs[gl + (q&1)];
      }
    }
  }
}

// ---------------------------------------------------------------------------
// K3: MMA expand + silu + residual, LN, MMA grouped conv #2, coalesced out
// ---------------------------------------------------------------------------
__global__ __launch_bounds__(256, 5) void k_freq2(
    float* __restrict__ out,
    const float* __restrict__ ew_, const float* __restrict__ eb_,
    const float* __restrict__ g2, const float* __restrict__ b2,
    const float* __restrict__ w2_, const float* __restrict__ cb2,
    const float* __restrict__ a2)
{
  extern __shared__ float sm[];
  float* xs  = sm;                 // [XROWS*68]
  float* ysb = xs + XROWS*XSS;     // [YROWS*68]; hqs (ne*20 tf32) aliases start
  float* wcg = ysb + YROWS*XSS;    // [8g][3kk][8c'][9] tf32 conv weights
  float* ewt = wcg + 8*3*8*9;      // [64*17]  tf32 [c][p]
  float* par = ewt + 64*17;        // eb|g2|b2|cb2 (64 each)
  float* ysc = ysb + XSS;
  float* hqs = ysb;                // aliased: dead once LN phase starts

  const int tid = threadIdx.x;
  const int n = blockIdx.x;
  const int b = n / TT, t = n % TT;
  const int f0 = blockIdx.y * CH;
  const int f1 = min(FR, f0 + CH);
  const int nf = f1 - f0;
  const int e0 = (f0 > 0) ? f0 - 1 : 0;
  const int e1 = (f1 < FR) ? f1 + 1 : FR;
  const int ne = e1 - e0;
  const int off = (f0 > 0) ? 1 : 0;

  if (tid < CC) {
    par[tid] = eb_[tid]; par[64+tid] = g2[tid];
    par[128+tid] = b2[tid]; par[192+tid] = cb2[tid];
  }
  for (int i = tid; i < 8*3*64; i += 256) {
    int g = i / 192, r = i % 192, kk = r >> 6, s = r & 63;
    int cp = s >> 3, ci = s & 7;
    wcg[((g*3+kk)*8 + cp)*9 + ci] = to_tf32(w2_[(g*8+cp)*24 + ci*3 + kk]);
  }
  for (int i = tid; i < CC*CPP; i += 256) {
    int c = i >> 4, p = i & 15;
    ewt[c*17 + p] = to_tf32(ew_[c*CPP + p]);
  }
  const float alpha = __ldg(a2);
  const float4* x1src = (const float4*)(g_x1 + ((size_t)n*FR + e0)*CC);
  for (int i = tid; i < ne*16; i += 256) {
    int r = i >> 4, q = i & 15;
    *(float4*)(xs + r*XSS + q*4) = x1src[i];
  }
  const float4* hqsrc = (const float4*)(g_hq + ((size_t)n*FR + e0)*CPP);
  for (int i = tid; i < ne*4; i += 256) {
    int r = i >> 2, q = i & 3;
    float4 v = hqsrc[i];
    v.x = to_tf32(v.x); v.y = to_tf32(v.y); v.z = to_tf32(v.z); v.w = to_tf32(v.w);
    *(float4*)(hqs + r*20 + q*4) = v;
  }
  __syncthreads();

  const int wid = tid >> 5, lane = tid & 31;
  const int grp = lane >> 2, tig = lane & 3;

  // MMA expand: warp w = c-tile w*8, 4 f-tiles of 16 (64 >= ne); silu+residual
  {
    float acc[4][4];
    #pragma unroll
    for (int mt = 0; mt < 4; ++mt)
      #pragma unroll
      for (int q = 0; q < 4; ++q) acc[mt][q] = 0.f;
    #pragma unroll
    for (int kc = 0; kc < 2; ++kc) {
      unsigned b0 = __float_as_uint(ewt[(wid*8+grp)*17 + kc*8 + tig]);
      unsigned b1 = __float_as_uint(ewt[(wid*8+grp)*17 + kc*8 + tig + 4]);
      #pragma unroll
      for (int mt = 0; mt < 4; ++mt) {
        unsigned a0 = __float_as_uint(hqs[(mt*16+grp)*20 + kc*8 + tig]);
        unsigned a1 = __float_as_uint(hqs[(mt*16+grp+8)*20 + kc*8 + tig]);
        unsigned a2 = __float_as_uint(hqs[(mt*16+grp)*20 + kc*8 + tig + 4]);
        unsigned a3 = __float_as_uint(hqs[(mt*16+grp+8)*20 + kc*8 + tig + 4]);
        MMA_TF32(acc[mt], a0,a1,a2,a3, b0,b1);
      }
    }
    __syncthreads();   // all hqs reads complete before xs update / ysb reuse
    #pragma unroll
    for (int mt = 0; mt < 4; ++mt)
      #pragma unroll
      for (int q = 0; q < 4; ++q) {
        int f = mt*16 + grp + ((q >> 1) << 3);
        int c = wid*8 + 2*tig + (q & 1);
        if (f < ne) {
          float v = acc[mt][q] + par[c];
          xs[f*XSS+c] += v/(1.f+__expf(-v));
        }
      }
  }
  __syncthreads();

  // zero only true halo rows (ysb now free), LN over all ne rows -> ysc (tf32)
  for (int i = tid; i < XSS; i += 256) {
    ysb[i] = 0.f;
    ysb[(ne+1)*XSS + i] = 0.f;
  }
  for (int r = wid; r < ne; r += 8) {
    float v0 = xs[r*XSS+lane], v1 = xs[r*XSS+lane+32];
    float s = v0+v1, q = v0*v0+v1*v1;
    WRED2(s,q)
    float m = s*(1.f/64.f);
    float rr = rsqrtf(fmaxf(q*(1.f/64.f)-m*m, 0.f)+LN_EPS);
    ysc[r*XSS+lane]    = to_tf32((v0-m)*rr*par[64+lane] + par[128+lane]);
    ysc[r*XSS+lane+32] = to_tf32((v1-m)*rr*par[96+lane] + par[160+lane]);
  }
  __syncthreads();

  // MMA grouped conv #2 + leaky + residual -> xs
  CONV_MMA(192, {
    int xr = fl + off;
    xs[xr*XSS + c] += lv;
  })
  __syncthreads();

  // coalesced copy xs rows [off, off+nf) -> out rows [f0, f1)
  float* obase = out + ((size_t)b*FR*TT + t)*CC;
  for (int i = tid; i < nf*16; i += 256) {
    int r = i >> 4, q = i & 15;
    *(float4*)(obase + (size_t)(f0+r)*TT*CC + q*4) =
        *(const float4*)(xs + (r+off)*XSS + q*4);
  }
}

// ---------------------------------------------------------------------------
extern "C" void kernel_launch(void* const* d_in, const int* in_sizes, int n_in,
                              void* d_out, int out_size)
{
  const float* h     = (const float*)d_in[0];
  const float* fc1g  = (const float*)d_in[1];
  const float* fc1b  = (const float*)d_in[2];
  const float* fc1w  = (const float*)d_in[3];
  const float* fc1cb = (const float*)d_in[4];
  const float* fc1a  = (const float*)d_in[5];
  const float* fblg  = (const float*)d_in[6];
  const float* fblb  = (const float*)d_in[7];
  const float* redw  = (const float*)d_in[8];
  const float* redb  = (const float*)d_in[9];
  const float* fW    = (const float*)d_in[10];
  const float* fB    = (const float*)d_in[11];
  const float* expw  = (const float*)d_in[12];
  const float* expb  = (const float*)d_in[13];
  const float* fc2g  = (const float*)d_in[14];
  const float* fc2b  = (const float*)d_in[15];
  const float* fc2w  = (const float*)d_in[16];
  const float* fc2cb = (const float*)d_in[17];
  const float* fc2a  = (const float*)d_in[18];
  float* out = (float*)d_out;

  const int SM1 = (XROWS*XSS + YROWS*XSS + 8*3*8*9 + 64*17 + 336) * 4;
  const int SM3 = (XROWS*XSS + YROWS*XSS + 8*3*8*9 + 64*17 + 256) * 4;
  cudaFuncSetAttribute(k_freq1, cudaFuncAttributeMaxDynamicSharedMemorySize, SM1);
  cudaFuncSetAttribute(k_freq2, cudaFuncAttributeMaxDynamicSharedMemorySize, SM3);

  k_prep<<<528, 256>>>(fW);
  dim3 g1(NN, NCH);
  k_freq1<<<g1, 256, SM1>>>(h, fc1g, fc1b, fc1w, fc1cb, fc1a,
                            fblg, fblb, redw, redb);
  dim3 gg((NN+127)/128, (FR+63)/64, CPP);
  k_fgemm<<<gg, 256>>>(fB);
  dim3 g3(NN, NCH);
  k_freq2<<<g3, 256, SM3>>>(out, expw, expb, fc2g, fc2b, fc2w, fc2cb, fc2a);
}